// round 2
// baseline (speedup 1.0000x reference)
#include <cuda_runtime.h>

#define IMG_H 512
#define IMG_W 512
#define OUT_H 506
#define OUT_W 506
#define TX 128   // output columns per block (= blockDim.x)
#define TY 64    // output rows per block

__device__ double g_acc;

__global__ void zero_kernel() { g_acc = 0.0; }

__global__ void __launch_bounds__(TX) ssim_kernel(const float* __restrict__ pred,
                                                  const float* __restrict__ targ)
{
    const int plane = blockIdx.z;
    const float* __restrict__ P = pred + (size_t)plane * IMG_H * IMG_W;
    const float* __restrict__ T = targ + (size_t)plane * IMG_H * IMG_W;
    const int x0 = blockIdx.x * TX;
    const int y0 = blockIdx.y * TY;
    const int cols = min(TX, OUT_W - x0);
    const int rows = min(TY, OUT_H - y0);
    const int incols = cols + 6;
    const int inrows = rows + 6;
    const int tid = threadIdx.x;
    const bool active = tid < cols;
    const bool load2 = tid < (incols - TX);   // tail columns (up to 6 threads)

    __shared__ float sp[2][TX + 8];
    __shared__ float st[2][TX + 8];

    float hist[5][7];
    float vsx = 0.f, vsy = 0.f, vsxx = 0.f, vsyy = 0.f, vsxy = 0.f;
    float acc = 0.f;

    // prefetch row 0 into registers
    {
        const float* pr = P + (size_t)y0 * IMG_W + x0;
        const float* tr = T + (size_t)y0 * IMG_W + x0;
        // incols >= 128 for every block in this problem, so tid load is safe
        sp[0][0] = 0.f; // (no-op touch; real stores below)
    }
    const float* pr0 = P + (size_t)y0 * IMG_W + x0;
    const float* tr0 = T + (size_t)y0 * IMG_W + x0;
    float p0 = pr0[tid];
    float t0 = tr0[tid];
    float p1 = load2 ? pr0[tid + TX] : 0.f;
    float t1 = load2 ? tr0[tid + TX] : 0.f;

    for (int base = 0; base < inrows; base += 7) {
        #pragma unroll
        for (int ph = 0; ph < 7; ++ph) {
            const int r = base + ph;
            if (r >= inrows) break;           // uniform across block
            const int buf = r & 1;

            // publish prefetched row r
            sp[buf][tid] = p0;
            st[buf][tid] = t0;
            if (load2) { sp[buf][tid + TX] = p1; st[buf][tid + TX] = t1; }
            __syncthreads();

            // prefetch row r+1 (LDG latency overlapped with compute below)
            if (r + 1 < inrows) {
                const float* pr = P + (size_t)(y0 + r + 1) * IMG_W + x0;
                const float* tr = T + (size_t)(y0 + r + 1) * IMG_W + x0;
                p0 = pr[tid]; t0 = tr[tid];
                if (load2) { p1 = pr[tid + TX]; t1 = tr[tid + TX]; }
            }

            // horizontal 7-tap sums for this thread's column
            float hx = 0.f, hy = 0.f, hxx = 0.f, hyy = 0.f, hxy = 0.f;
            if (active) {
                #pragma unroll
                for (int dx = 0; dx < 7; ++dx) {
                    const float p = sp[buf][tid + dx];
                    const float t = st[buf][tid + dx];
                    hx += p;
                    hy += t;
                    hxx = fmaf(p, p, hxx);
                    hyy = fmaf(t, t, hyy);
                    hxy = fmaf(p, t, hxy);
                }
            }

            // vertical sliding window (ring index ph is compile-time: no spill)
            if (r >= 7) {
                vsx  -= hist[0][ph];
                vsy  -= hist[1][ph];
                vsxx -= hist[2][ph];
                vsyy -= hist[3][ph];
                vsxy -= hist[4][ph];
            }
            hist[0][ph] = hx; hist[1][ph] = hy;
            hist[2][ph] = hxx; hist[3][ph] = hyy; hist[4][ph] = hxy;
            vsx += hx; vsy += hy; vsxx += hxx; vsyy += hyy; vsxy += hxy;

            if (r >= 6 && active) {
                const float inv = 1.0f / 49.0f;
                const float cov = 49.0f / 48.0f;
                const float C1 = 0.0004f;   // (0.01*2)^2
                const float C2 = 0.0036f;   // (0.03*2)^2
                const float ux  = vsx  * inv;
                const float uy  = vsy  * inv;
                const float uxx = vsxx * inv;
                const float uyy = vsyy * inv;
                const float uxy = vsxy * inv;
                const float vx  = cov * (uxx - ux * ux);
                const float vy  = cov * (uyy - uy * uy);
                const float vxy = cov * (uxy - ux * uy);
                const float num = (2.f * ux * uy + C1) * (2.f * vxy + C2);
                const float den = (ux * ux + uy * uy + C1) * (vx + vy + C2);
                acc += __fdividef(num, den);
            }
        }
    }

    // block reduction -> one double atomic per block
    #pragma unroll
    for (int off = 16; off > 0; off >>= 1)
        acc += __shfl_down_sync(0xffffffffu, acc, off);

    __shared__ float wsum[TX / 32];
    if ((tid & 31) == 0) wsum[tid >> 5] = acc;
    __syncthreads();
    if (tid == 0) {
        float s = 0.f;
        #pragma unroll
        for (int w = 0; w < TX / 32; ++w) s += wsum[w];
        atomicAdd(&g_acc, (double)s);
    }
}

__global__ void finalize_kernel(float* __restrict__ out, double inv_count)
{
    out[0] = 1.0f - (float)(g_acc * inv_count);
}

extern "C" void kernel_launch(void* const* d_in, const int* in_sizes, int n_in,
                              void* d_out, int out_size)
{
    const float* pred = (const float*)d_in[0];
    const float* targ = (const float*)d_in[1];
    const int planes = in_sizes[0] / (IMG_H * IMG_W);   // 96 for [32,3,512,512]

    zero_kernel<<<1, 1>>>();

    dim3 grid((OUT_W + TX - 1) / TX, (OUT_H + TY - 1) / TY, planes);
    ssim_kernel<<<grid, TX>>>(pred, targ);

    const double inv_count = 1.0 / ((double)planes * OUT_H * OUT_W);
    finalize_kernel<<<1, 1>>>((float*)d_out, inv_count);
}

// round 3
// speedup vs baseline: 1.1455x; 1.1455x over previous
#include <cuda_runtime.h>

#define IMG_H 512
#define IMG_W 512
#define OUT_H 506
#define OUT_W 506
#define NT 128          // threads per block
#define BX 256          // output columns per block (2 per thread)
#define BY 102          // output rows per block

__device__ double g_acc;

__global__ void zero_kernel() { g_acc = 0.0; }

__global__ void __launch_bounds__(NT) ssim_kernel(const float* __restrict__ pred,
                                                  const float* __restrict__ targ)
{
    const int plane = blockIdx.z;
    const float* __restrict__ P = pred + (size_t)plane * IMG_H * IMG_W;
    const float* __restrict__ T = targ + (size_t)plane * IMG_H * IMG_W;
    const int x0 = blockIdx.x * BX;
    const int y0 = blockIdx.y * BY;
    const int cols = min(BX, OUT_W - x0);      // 256 or 250
    const int rows = min(BY, OUT_H - y0);      // 102 or 98
    const int incols = cols + 6;
    const int inrows = rows + 6;
    const int tid = threadIdx.x;
    const bool act0 = 2 * tid < cols;
    const bool act1 = 2 * tid + 1 < cols;
    const int tailpairs = (incols - 2 * NT + 1) >> 1;   // 3 for full block, 0 for tail block
    const bool loadtail = tid < tailpairs;

    // double-buffered input rows as float2 (element 2k, 2k+1 at index k)
    __shared__ float2 sp[2][132];
    __shared__ float2 st[2][132];

    // zero the read-but-maybe-unwritten tail region (tail-x block)
    if (tid < 4) {
        float2 z = make_float2(0.f, 0.f);
        sp[0][128 + tid] = z; sp[1][128 + tid] = z;
        st[0][128 + tid] = z; st[1][128 + tid] = z;
    }

    // vertical sliding state: [col][quantity]  (quantities: x, y, xx, yy, xy)
    float hist[2][5][7];
    float v0x = 0.f, v0y = 0.f, v0xx = 0.f, v0yy = 0.f, v0xy = 0.f;
    float v1x = 0.f, v1y = 0.f, v1xx = 0.f, v1yy = 0.f, v1xy = 0.f;
    float acc = 0.f;

    // prefetch row 0
    const float2* pr0 = (const float2*)(P + (size_t)y0 * IMG_W + x0);
    const float2* tr0 = (const float2*)(T + (size_t)y0 * IMG_W + x0);
    float2 pf = pr0[tid];
    float2 tf = tr0[tid];
    float2 pf2 = loadtail ? pr0[NT + tid] : make_float2(0.f, 0.f);
    float2 tf2 = loadtail ? tr0[NT + tid] : make_float2(0.f, 0.f);

    for (int base = 0; base < inrows; base += 7) {
        #pragma unroll
        for (int ph = 0; ph < 7; ++ph) {
            const int r = base + ph;
            if (r >= inrows) break;            // uniform across block
            const int buf = r & 1;

            // publish prefetched row r
            sp[buf][tid] = pf;
            st[buf][tid] = tf;
            if (loadtail) { sp[buf][NT + tid] = pf2; st[buf][NT + tid] = tf2; }
            __syncthreads();

            // prefetch row r+1 (overlaps LDG latency with compute)
            if (r + 1 < inrows) {
                const float2* pr = (const float2*)(P + (size_t)(y0 + r + 1) * IMG_W + x0);
                const float2* tr = (const float2*)(T + (size_t)(y0 + r + 1) * IMG_W + x0);
                pf = pr[tid]; tf = tr[tid];
                if (loadtail) { pf2 = pr[NT + tid]; tf2 = tr[NT + tid]; }
            }

            // load the 8-element union window for the two columns
            const float2 a0 = sp[buf][tid];     const float2 b0 = st[buf][tid];
            const float2 a1 = sp[buf][tid + 1]; const float2 b1 = st[buf][tid + 1];
            const float2 a2 = sp[buf][tid + 2]; const float2 b2 = st[buf][tid + 2];
            const float2 a3 = sp[buf][tid + 3]; const float2 b3 = st[buf][tid + 3];
            const float p0 = a0.x, p1 = a0.y, p2 = a1.x, p3 = a1.y,
                        p4 = a2.x, p5 = a2.y, p6 = a3.x, p7 = a3.y;
            const float t0 = b0.x, t1 = b0.y, t2 = b1.x, t3 = b1.y,
                        t4 = b2.x, t5 = b2.y, t6 = b3.x, t7 = b3.y;

            // horizontal 7-tap sums for col A (taps 0..6) and col B (taps 1..7)
            const float hxA = ((p0 + p1) + (p2 + p3)) + ((p4 + p5) + p6);
            const float hyA = ((t0 + t1) + (t2 + t3)) + ((t4 + t5) + t6);
            const float hxB = hxA - p0 + p7;
            const float hyB = hyA - t0 + t7;
            const float qx0 = p0 * p0, qx7 = p7 * p7;
            const float qy0 = t0 * t0, qy7 = t7 * t7;
            const float qz0 = p0 * t0, qz7 = p7 * t7;
            float hxxA = fmaf(p1, p1, qx0);
            hxxA = fmaf(p2, p2, hxxA); hxxA = fmaf(p3, p3, hxxA);
            hxxA = fmaf(p4, p4, hxxA); hxxA = fmaf(p5, p5, hxxA);
            hxxA = fmaf(p6, p6, hxxA);
            float hyyA = fmaf(t1, t1, qy0);
            hyyA = fmaf(t2, t2, hyyA); hyyA = fmaf(t3, t3, hyyA);
            hyyA = fmaf(t4, t4, hyyA); hyyA = fmaf(t5, t5, hyyA);
            hyyA = fmaf(t6, t6, hyyA);
            float hxyA = fmaf(p1, t1, qz0);
            hxyA = fmaf(p2, t2, hxyA); hxyA = fmaf(p3, t3, hxyA);
            hxyA = fmaf(p4, t4, hxyA); hxyA = fmaf(p5, t5, hxyA);
            hxyA = fmaf(p6, t6, hxyA);
            const float hxxB = hxxA - qx0 + qx7;
            const float hyyB = hyyA - qy0 + qy7;
            const float hxyB = hxyA - qz0 + qz7;

            // vertical sliding window (ring index ph is compile-time)
            if (r >= 7) {
                v0x -= hist[0][0][ph]; v0y -= hist[0][1][ph]; v0xx -= hist[0][2][ph];
                v0yy -= hist[0][3][ph]; v0xy -= hist[0][4][ph];
                v1x -= hist[1][0][ph]; v1y -= hist[1][1][ph]; v1xx -= hist[1][2][ph];
                v1yy -= hist[1][3][ph]; v1xy -= hist[1][4][ph];
            }
            hist[0][0][ph] = hxA; hist[0][1][ph] = hyA; hist[0][2][ph] = hxxA;
            hist[0][3][ph] = hyyA; hist[0][4][ph] = hxyA;
            hist[1][0][ph] = hxB; hist[1][1][ph] = hyB; hist[1][2][ph] = hxxB;
            hist[1][3][ph] = hyyB; hist[1][4][ph] = hxyB;
            v0x += hxA; v0y += hyA; v0xx += hxxA; v0yy += hyyA; v0xy += hxyA;
            v1x += hxB; v1y += hyB; v1xx += hxxB; v1yy += hyyB; v1xy += hxyB;

            if (r >= 6) {
                // unnormalized SSIM: 1/49 scalings cancel between num and den
                const float A = 0.96040004f;        // C1 * 49^2
                const float B = 8.6436f;            // C2 * 49^2
                const float Q = 49.0f / 48.0f;
                if (act0) {
                    const float sxy = v0x * v0y;
                    const float n1 = fmaf(2.f, sxy, A);
                    const float cc = fmaf(49.f, v0xy, -sxy);
                    const float n2 = fmaf(2.f * Q, cc, B);
                    const float s2 = fmaf(v0x, v0x, v0y * v0y);
                    const float d1 = s2 + A;
                    const float tt = fmaf(49.f, v0xx + v0yy, -s2);
                    const float d2 = fmaf(Q, tt, B);
                    acc += __fdividef(n1 * n2, d1 * d2);
                }
                if (act1) {
                    const float sxy = v1x * v1y;
                    const float n1 = fmaf(2.f, sxy, A);
                    const float cc = fmaf(49.f, v1xy, -sxy);
                    const float n2 = fmaf(2.f * Q, cc, B);
                    const float s2 = fmaf(v1x, v1x, v1y * v1y);
                    const float d1 = s2 + A;
                    const float tt = fmaf(49.f, v1xx + v1yy, -s2);
                    const float d2 = fmaf(Q, tt, B);
                    acc += __fdividef(n1 * n2, d1 * d2);
                }
            }
        }
    }

    // block reduction -> one double atomic per block
    #pragma unroll
    for (int off = 16; off > 0; off >>= 1)
        acc += __shfl_down_sync(0xffffffffu, acc, off);

    __shared__ float wsum[NT / 32];
    if ((tid & 31) == 0) wsum[tid >> 5] = acc;
    __syncthreads();
    if (tid == 0) {
        float s = 0.f;
        #pragma unroll
        for (int w = 0; w < NT / 32; ++w) s += wsum[w];
        atomicAdd(&g_acc, (double)s);
    }
}

__global__ void finalize_kernel(float* __restrict__ out, double inv_count)
{
    out[0] = 1.0f - (float)(g_acc * inv_count);
}

extern "C" void kernel_launch(void* const* d_in, const int* in_sizes, int n_in,
                              void* d_out, int out_size)
{
    const float* pred = (const float*)d_in[0];
    const float* targ = (const float*)d_in[1];
    const int planes = in_sizes[0] / (IMG_H * IMG_W);   // 96 for [32,3,512,512]

    zero_kernel<<<1, 1>>>();

    dim3 grid((OUT_W + BX - 1) / BX, (OUT_H + BY - 1) / BY, planes);
    ssim_kernel<<<grid, NT>>>(pred, targ);

    const double inv_count = 1.0 / ((double)planes * OUT_H * OUT_W);
    finalize_kernel<<<1, 1>>>((float*)d_out, inv_count);
}

// round 4
// speedup vs baseline: 1.1699x; 1.0213x over previous
#include <cuda_runtime.h>

#define IMG_H 512
#define IMG_W 512
#define OUT_H 506
#define OUT_W 506
#define STRIP_OUT 58     // output columns per warp strip (64 input cols)
#define STRIPS_X 9       // ceil(506/58)
#define HALF_ROWS 253    // 506 = 2*253
#define IN_ROWS 259      // 253+6 = 7*37, exact unroll
#define WPB 4            // warps per block
#define NT 128

typedef unsigned long long u64;

__device__ double g_acc;

__global__ void zero_kernel() { g_acc = 0.0; }

__device__ __forceinline__ u64 pack2(float lo, float hi) {
    u64 r; asm("mov.b64 %0, {%1, %2};" : "=l"(r) : "f"(lo), "f"(hi)); return r;
}
__device__ __forceinline__ void unpack2(u64 v, float& lo, float& hi) {
    asm("mov.b64 {%0, %1}, %2;" : "=f"(lo), "=f"(hi) : "l"(v));
}
__device__ __forceinline__ u64 add2(u64 a, u64 b) {
    u64 r; asm("add.rn.f32x2 %0, %1, %2;" : "=l"(r) : "l"(a), "l"(b)); return r;
}
__device__ __forceinline__ u64 mul2(u64 a, u64 b) {
    u64 r; asm("mul.rn.f32x2 %0, %1, %2;" : "=l"(r) : "l"(a), "l"(b)); return r;
}
__device__ __forceinline__ u64 fma2(u64 a, u64 b, u64 c) {
    u64 r; asm("fma.rn.f32x2 %0, %1, %2, %3;" : "=l"(r) : "l"(a), "l"(b), "l"(c)); return r;
}
// a - b computed as fma(b, {-1,-1}, a)  (exact, avoids relying on sub.f32x2)
__device__ __forceinline__ u64 sub2(u64 a, u64 b, u64 neg1) { return fma2(b, neg1, a); }

__device__ __forceinline__ u64 shfl_dn64(u64 v, int d) {
    unsigned lo = (unsigned)v, hi = (unsigned)(v >> 32);
    lo = __shfl_down_sync(0xffffffffu, lo, d);
    hi = __shfl_down_sync(0xffffffffu, hi, d);
    return ((u64)hi << 32) | lo;
}

__global__ void __launch_bounds__(NT, 3) ssim_kernel(const float* __restrict__ pred,
                                                     const float* __restrict__ targ)
{
    const int wid  = blockIdx.x * WPB + (threadIdx.x >> 5);   // 0..1727
    const int lane = threadIdx.x & 31;
    const int plane = wid / 18;                // 18 warps per plane
    const int rem   = wid - plane * 18;
    const int half  = rem / STRIPS_X;
    const int sx    = rem - half * STRIPS_X;

    const float* __restrict__ Pb = pred + (size_t)plane * IMG_H * IMG_W;
    const float* __restrict__ Tb = targ + (size_t)plane * IMG_H * IMG_W;
    const int x0 = sx * STRIP_OUT;             // output & input col start
    const int y0 = half * HALF_ROWS;           // input row start
    const int gx = x0 + 2 * lane;              // this thread's 2 input cols
    const bool inb = gx < IMG_W;               // gx even -> gx<512 implies gx+1<512
    const int cols_valid = min(STRIP_OUT, OUT_W - x0);
    const bool act0 = (2 * lane)     < cols_valid;
    const bool act1 = (2 * lane + 1) < cols_valid;

    const u64 NEG1 = pack2(-1.f, -1.f);

    // vertical sliding state per column (A = 2*lane, B = 2*lane+1)
    u64 VA = 0, VqA = 0, VB = 0, VqB = 0;      // {Sx,Sy}, {Sxx,Syy} (0.0 bits = {0,0})
    float vxyA = 0.f, vxyB = 0.f;
    u64 histH[2][7], histQ[2][7];
    float histXY[2][7];
    float acc = 0.f;

    const float* pp = Pb + (size_t)y0 * IMG_W + gx;
    const float* tp = Tb + (size_t)y0 * IMG_W + gx;
    float2 pf = make_float2(0.f, 0.f), tf = make_float2(0.f, 0.f);
    if (inb) { pf = *(const float2*)pp; tf = *(const float2*)tp; }
    pp += IMG_W; tp += IMG_W;

    #pragma unroll 1
    for (int base = 0; base < 37; ++base) {
        #pragma unroll
        for (int ph = 0; ph < 7; ++ph) {
            const int r = base * 7 + ph;

            // pack (pred,target) pairs for this row
            const u64 w0 = pack2(pf.x, tf.x);
            const u64 w1 = pack2(pf.y, tf.y);

            // prefetch next row (overlaps with compute below)
            float2 pn = make_float2(0.f, 0.f), tn = make_float2(0.f, 0.f);
            if (inb && (r + 1 < IN_ROWS)) { pn = *(const float2*)pp; tn = *(const float2*)tp; }
            pp += IMG_W; tp += IMG_W;

            // halo from neighbor lanes (strip fits in one warp)
            const u64 w2 = shfl_dn64(w0, 1);
            const u64 w3 = shfl_dn64(w1, 1);
            const u64 w4 = shfl_dn64(w0, 2);
            const u64 w5 = shfl_dn64(w1, 2);
            const u64 w6 = shfl_dn64(w0, 3);
            const u64 w7 = shfl_dn64(w1, 3);

            // horizontal 7-tap sums, packed {x,y}
            const u64 H  = add2(add2(add2(w0, w1), add2(w2, w3)),
                                add2(add2(w4, w5), w6));           // {hxA,hyA}
            const u64 HB = add2(sub2(H, w0, NEG1), w7);            // {hxB,hyB}
            const u64 q0 = mul2(w0, w0);
            u64 Q = q0;
            Q = fma2(w1, w1, Q); Q = fma2(w2, w2, Q); Q = fma2(w3, w3, Q);
            Q = fma2(w4, w4, Q); Q = fma2(w5, w5, Q); Q = fma2(w6, w6, Q); // {hxxA,hyyA}
            const u64 q7 = mul2(w7, w7);
            const u64 QB = add2(sub2(Q, q0, NEG1), q7);            // {hxxB,hyyB}

            // cross terms (scalar)
            float p0, t0, p1, t1, p2, t2, p3, t3, p4, t4, p5, t5, p6, t6, p7, t7;
            unpack2(w0, p0, t0); unpack2(w1, p1, t1); unpack2(w2, p2, t2);
            unpack2(w3, p3, t3); unpack2(w4, p4, t4); unpack2(w5, p5, t5);
            unpack2(w6, p6, t6); unpack2(w7, p7, t7);
            const float u0 = p0 * t0;
            float hxyA = fmaf(p1, t1, u0);
            hxyA = fmaf(p2, t2, hxyA); hxyA = fmaf(p3, t3, hxyA);
            hxyA = fmaf(p4, t4, hxyA); hxyA = fmaf(p5, t5, hxyA);
            hxyA = fmaf(p6, t6, hxyA);
            const float u7 = p7 * t7;
            const float hxyB = hxyA - u0 + u7;

            // vertical sliding window (ring index ph is compile-time)
            if (r >= 7) {
                VA = sub2(VA, histH[0][ph], NEG1); VqA = sub2(VqA, histQ[0][ph], NEG1);
                vxyA -= histXY[0][ph];
                VB = sub2(VB, histH[1][ph], NEG1); VqB = sub2(VqB, histQ[1][ph], NEG1);
                vxyB -= histXY[1][ph];
            }
            histH[0][ph] = H;  histQ[0][ph] = Q;  histXY[0][ph] = hxyA;
            histH[1][ph] = HB; histQ[1][ph] = QB; histXY[1][ph] = hxyB;
            VA = add2(VA, H);  VqA = add2(VqA, Q);  vxyA += hxyA;
            VB = add2(VB, HB); VqB = add2(VqB, QB); vxyB += hxyB;

            if (r >= 6) {
                // unnormalized SSIM (1/49 cancels): A=C1*49^2, B=C2*49^2
                const float Ac = 0.96040004f;
                const float Bc = 8.6436f;
                const float Qc = 49.0f / 48.0f;
                if (act0) {
                    float vsx, vsy, vsxx, vsyy;
                    unpack2(VA, vsx, vsy); unpack2(VqA, vsxx, vsyy);
                    const float sxy = vsx * vsy;
                    const float n1  = fmaf(2.f, sxy, Ac);
                    const float cc  = fmaf(49.f, vxyA, -sxy);
                    const float n2  = fmaf(2.f * Qc, cc, Bc);
                    const float s2  = fmaf(vsx, vsx, vsy * vsy);
                    const float d1  = s2 + Ac;
                    const float tt  = fmaf(49.f, vsxx + vsyy, -s2);
                    const float d2  = fmaf(Qc, tt, Bc);
                    acc += __fdividef(n1 * n2, d1 * d2);
                }
                if (act1) {
                    float vsx, vsy, vsxx, vsyy;
                    unpack2(VB, vsx, vsy); unpack2(VqB, vsxx, vsyy);
                    const float sxy = vsx * vsy;
                    const float n1  = fmaf(2.f, sxy, Ac);
                    const float cc  = fmaf(49.f, vxyB, -sxy);
                    const float n2  = fmaf(2.f * Qc, cc, Bc);
                    const float s2  = fmaf(vsx, vsx, vsy * vsy);
                    const float d1  = s2 + Ac;
                    const float tt  = fmaf(49.f, vsxx + vsyy, -s2);
                    const float d2  = fmaf(Qc, tt, Bc);
                    acc += __fdividef(n1 * n2, d1 * d2);
                }
            }

            pf = pn; tf = tn;
        }
    }

    // warp reduction -> one double atomic per warp (no smem, no block sync)
    #pragma unroll
    for (int off = 16; off > 0; off >>= 1)
        acc += __shfl_down_sync(0xffffffffu, acc, off);
    if (lane == 0)
        atomicAdd(&g_acc, (double)acc);
}

__global__ void finalize_kernel(float* __restrict__ out, double inv_count)
{
    out[0] = 1.0f - (float)(g_acc * inv_count);
}

extern "C" void kernel_launch(void* const* d_in, const int* in_sizes, int n_in,
                              void* d_out, int out_size)
{
    const float* pred = (const float*)d_in[0];
    const float* targ = (const float*)d_in[1];
    const int planes = in_sizes[0] / (IMG_H * IMG_W);   // 96

    zero_kernel<<<1, 1>>>();

    const int warps = planes * 2 * STRIPS_X;            // 1728
    const int blocks = warps / WPB;                     // 432
    ssim_kernel<<<blocks, NT>>>(pred, targ);

    const double inv_count = 1.0 / ((double)planes * OUT_H * OUT_W);
    finalize_kernel<<<1, 1>>>((float*)d_out, inv_count);
}

// round 5
// speedup vs baseline: 1.5485x; 1.3236x over previous
#include <cuda_runtime.h>

#define IMG_H 512
#define IMG_W 512
#define OUT_H 506
#define OUT_W 506
#define STRIP_OUT 58     // output columns per warp strip (64 input cols)
#define STRIPS_X 9       // ceil(506/58)
#define HALF_ROWS 253    // 506 = 2*253
#define IN_ROWS 259      // 253+6 = 7*37, exact unroll
#define WPB 4            // warps per block
#define NT 128
#define DEPTH 8          // cp.async pipeline stages
#define STG_F2 36        // float2 slots per stage (32 data + 4 pad for halo reads)

typedef unsigned long long u64;

__device__ double g_acc;        // zero-initialized at module load; self-reset each launch
__device__ unsigned g_count;    // wraps to 0 via atomicInc each launch

__device__ __forceinline__ u64 pack2(float lo, float hi) {
    u64 r; asm("mov.b64 %0, {%1, %2};" : "=l"(r) : "f"(lo), "f"(hi)); return r;
}
__device__ __forceinline__ void unpack2(u64 v, float& lo, float& hi) {
    asm("mov.b64 {%0, %1}, %2;" : "=f"(lo), "=f"(hi) : "l"(v));
}
__device__ __forceinline__ u64 add2(u64 a, u64 b) {
    u64 r; asm("add.rn.f32x2 %0, %1, %2;" : "=l"(r) : "l"(a), "l"(b)); return r;
}
__device__ __forceinline__ u64 mul2(u64 a, u64 b) {
    u64 r; asm("mul.rn.f32x2 %0, %1, %2;" : "=l"(r) : "l"(a), "l"(b)); return r;
}
__device__ __forceinline__ u64 fma2(u64 a, u64 b, u64 c) {
    u64 r; asm("fma.rn.f32x2 %0, %1, %2, %3;" : "=l"(r) : "l"(a), "l"(b), "l"(c)); return r;
}
__device__ __forceinline__ u64 sub2(u64 a, u64 b, u64 neg1) { return fma2(b, neg1, a); }

__device__ __forceinline__ void cp_async8(unsigned dst, const void* src, int src_bytes) {
    asm volatile("cp.async.ca.shared.global [%0], [%1], 8, %2;"
                 :: "r"(dst), "l"(src), "r"(src_bytes));
}
__device__ __forceinline__ void cp_commit() { asm volatile("cp.async.commit_group;"); }
__device__ __forceinline__ void cp_wait7()  { asm volatile("cp.async.wait_group 7;"); }

__global__ void __launch_bounds__(NT, 3) ssim_kernel(const float* __restrict__ pred,
                                                     const float* __restrict__ targ,
                                                     float* __restrict__ out,
                                                     double inv_count, unsigned nblk)
{
    __shared__ float2 pbuf[WPB][DEPTH][STG_F2];
    __shared__ float2 tbuf[WPB][DEPTH][STG_F2];

    const int w    = threadIdx.x >> 5;
    const int lane = threadIdx.x & 31;
    const int wid  = blockIdx.x * WPB + w;                // 0..1727
    const int plane = wid / 18;                           // 18 warps per plane
    const int rem   = wid - plane * 18;
    const int half  = rem / STRIPS_X;
    const int sx    = rem - half * STRIPS_X;

    const int x0 = sx * STRIP_OUT;
    const int y0 = half * HALF_ROWS;
    const int gx = x0 + 2 * lane;
    const bool inb = gx < IMG_W;
    const int sz = inb ? 8 : 0;                           // cp.async src-size (0 = zero-fill)
    const int cols_valid = min(STRIP_OUT, OUT_W - x0);
    const bool act0 = (2 * lane)     < cols_valid;
    const bool act1 = (2 * lane + 1) < cols_valid;

    const float* gp = pred + (size_t)plane * IMG_H * IMG_W + (size_t)y0 * IMG_W + gx;
    const float* gt = targ + (size_t)plane * IMG_H * IMG_W + (size_t)y0 * IMG_W + gx;

    const unsigned dp0 = (unsigned)__cvta_generic_to_shared(&pbuf[w][0][lane]);
    const unsigned dt0 = (unsigned)__cvta_generic_to_shared(&tbuf[w][0][lane]);
    const unsigned STG_B = STG_F2 * 8;                    // 288 bytes per stage

    // prologue: stage rows 0..6
    #pragma unroll
    for (int i = 0; i < DEPTH - 1; ++i) {
        cp_async8(dp0 + i * STG_B, gp, sz);
        cp_async8(dt0 + i * STG_B, gt, sz);
        gp += IMG_W; gt += IMG_W;
        cp_commit();
    }

    const u64 NEG1 = pack2(-1.f, -1.f);
    u64 VA = 0, VqA = 0, VB = 0, VqB = 0;                 // {Sx,Sy},{Sxx,Syy} per col
    float vxyA = 0.f, vxyB = 0.f;
    u64 histH[2][7], histQ[2][7];
    float histXY[2][7];
    float acc = 0.f;

    #pragma unroll 1
    for (int base = 0; base < 37; ++base) {
        #pragma unroll
        for (int ph = 0; ph < 7; ++ph) {
            const int r = base * 7 + ph;

            // issue row r+7 into the stage consumed last iteration
            if (r + DEPTH - 1 < IN_ROWS) {
                const unsigned so = ((unsigned)(r + DEPTH - 1) & (DEPTH - 1)) * STG_B;
                cp_async8(dp0 + so, gp, sz);
                cp_async8(dt0 + so, gt, sz);
                gp += IMG_W; gt += IMG_W;
            }
            cp_commit();            // empty group near tail keeps numbering aligned
            cp_wait7();             // row r's group retired

            const int s = r & (DEPTH - 1);
            const float2 a0 = pbuf[w][s][lane];     const float2 b0 = tbuf[w][s][lane];
            const float2 a1 = pbuf[w][s][lane + 1]; const float2 b1 = tbuf[w][s][lane + 1];
            const float2 a2 = pbuf[w][s][lane + 2]; const float2 b2 = tbuf[w][s][lane + 2];
            const float2 a3 = pbuf[w][s][lane + 3]; const float2 b3 = tbuf[w][s][lane + 3];

            const u64 w0 = pack2(a0.x, b0.x), w1 = pack2(a0.y, b0.y);
            const u64 w2 = pack2(a1.x, b1.x), w3 = pack2(a1.y, b1.y);
            const u64 w4 = pack2(a2.x, b2.x), w5 = pack2(a2.y, b2.y);
            const u64 w6 = pack2(a3.x, b3.x), w7 = pack2(a3.y, b3.y);

            // horizontal 7-tap sums, packed {x,y}
            const u64 H  = add2(add2(add2(w0, w1), add2(w2, w3)),
                                add2(add2(w4, w5), w6));           // {hxA,hyA}
            const u64 HB = add2(sub2(H, w0, NEG1), w7);            // {hxB,hyB}
            const u64 q0 = mul2(w0, w0);
            u64 Q = q0;
            Q = fma2(w1, w1, Q); Q = fma2(w2, w2, Q); Q = fma2(w3, w3, Q);
            Q = fma2(w4, w4, Q); Q = fma2(w5, w5, Q); Q = fma2(w6, w6, Q);
            const u64 q7 = mul2(w7, w7);
            const u64 QB = add2(sub2(Q, q0, NEG1), q7);            // {hxxB,hyyB}

            // cross terms (scalar)
            const float u0 = a0.x * b0.x;
            float hxyA = fmaf(a0.y, b0.y, u0);
            hxyA = fmaf(a1.x, b1.x, hxyA); hxyA = fmaf(a1.y, b1.y, hxyA);
            hxyA = fmaf(a2.x, b2.x, hxyA); hxyA = fmaf(a2.y, b2.y, hxyA);
            hxyA = fmaf(a3.x, b3.x, hxyA);
            const float u7 = a3.y * b3.y;
            const float hxyB = hxyA - u0 + u7;

            // vertical sliding window (ring index ph is compile-time)
            if (r >= 7) {
                VA = sub2(VA, histH[0][ph], NEG1); VqA = sub2(VqA, histQ[0][ph], NEG1);
                vxyA -= histXY[0][ph];
                VB = sub2(VB, histH[1][ph], NEG1); VqB = sub2(VqB, histQ[1][ph], NEG1);
                vxyB -= histXY[1][ph];
            }
            histH[0][ph] = H;  histQ[0][ph] = Q;  histXY[0][ph] = hxyA;
            histH[1][ph] = HB; histQ[1][ph] = QB; histXY[1][ph] = hxyB;
            VA = add2(VA, H);  VqA = add2(VqA, Q);  vxyA += hxyA;
            VB = add2(VB, HB); VqB = add2(VqB, QB); vxyB += hxyB;

            if (r >= 6) {
                const float Ac = 0.96040004f;   // C1 * 49^2
                const float Bc = 8.6436f;       // C2 * 49^2
                const float Qc = 49.0f / 48.0f;
                if (act0) {
                    float vsx, vsy, vsxx, vsyy;
                    unpack2(VA, vsx, vsy); unpack2(VqA, vsxx, vsyy);
                    const float sxy = vsx * vsy;
                    const float n1  = fmaf(2.f, sxy, Ac);
                    const float cc  = fmaf(49.f, vxyA, -sxy);
                    const float n2  = fmaf(2.f * Qc, cc, Bc);
                    const float s2  = fmaf(vsx, vsx, vsy * vsy);
                    const float d1  = s2 + Ac;
                    const float tt  = fmaf(49.f, vsxx + vsyy, -s2);
                    const float d2  = fmaf(Qc, tt, Bc);
                    acc += __fdividef(n1 * n2, d1 * d2);
                }
                if (act1) {
                    float vsx, vsy, vsxx, vsyy;
                    unpack2(VB, vsx, vsy); unpack2(VqB, vsxx, vsyy);
                    const float sxy = vsx * vsy;
                    const float n1  = fmaf(2.f, sxy, Ac);
                    const float cc  = fmaf(49.f, vxyB, -sxy);
                    const float n2  = fmaf(2.f * Qc, cc, Bc);
                    const float s2  = fmaf(vsx, vsx, vsy * vsy);
                    const float d1  = s2 + Ac;
                    const float tt  = fmaf(49.f, vsxx + vsyy, -s2);
                    const float d2  = fmaf(Qc, tt, Bc);
                    acc += __fdividef(n1 * n2, d1 * d2);
                }
            }
        }
    }

    // warp reduce -> atomic; last block finalizes and resets state for graph replay
    #pragma unroll
    for (int off = 16; off > 0; off >>= 1)
        acc += __shfl_down_sync(0xffffffffu, acc, off);
    if (lane == 0)
        atomicAdd(&g_acc, (double)acc);
    __syncthreads();
    if (threadIdx.x == 0) {
        __threadfence();
        const unsigned old = atomicInc(&g_count, nblk - 1);   // wraps to 0 on last block
        if (old == nblk - 1) {
            __threadfence();
            const double v = atomicAdd(&g_acc, 0.0);
            out[0] = 1.0f - (float)(v * inv_count);
            __threadfence();
            g_acc = 0.0;                                      // ready for next replay
        }
    }
}

extern "C" void kernel_launch(void* const* d_in, const int* in_sizes, int n_in,
                              void* d_out, int out_size)
{
    const float* pred = (const float*)d_in[0];
    const float* targ = (const float*)d_in[1];
    const int planes = in_sizes[0] / (IMG_H * IMG_W);     // 96

    const unsigned warps  = planes * 2 * STRIPS_X;        // 1728
    const unsigned blocks = warps / WPB;                  // 432
    const double inv_count = 1.0 / ((double)planes * OUT_H * OUT_W);

    ssim_kernel<<<blocks, NT>>>(pred, targ, (float*)d_out, inv_count, blocks);
}

// round 6
// speedup vs baseline: 2.1857x; 1.4115x over previous
#include <cuda_runtime.h>

#define IMG_H 512
#define IMG_W 512
#define OUT_H 506
#define OUT_W 506
#define BAND  46      // output rows per warp band (506 = 11*46)
#define NBANDS 11
#define INROWS 52     // BAND + 6

typedef unsigned long long u64;

__device__ double g_acc;        // zero at module load; self-reset each launch
__device__ unsigned g_count;    // wraps to 0 via atomicInc each launch

__device__ __forceinline__ u64 pack2(float lo, float hi) {
    u64 r; asm("mov.b64 %0, {%1, %2};" : "=l"(r) : "f"(lo), "f"(hi)); return r;
}
__device__ __forceinline__ void unpack2(u64 v, float& lo, float& hi) {
    asm("mov.b64 {%0, %1}, %2;" : "=f"(lo), "=f"(hi) : "l"(v));
}
__device__ __forceinline__ u64 add2(u64 a, u64 b) {
    u64 r; asm("add.rn.f32x2 %0, %1, %2;" : "=l"(r) : "l"(a), "l"(b)); return r;
}
__device__ __forceinline__ u64 mul2(u64 a, u64 b) {
    u64 r; asm("mul.rn.f32x2 %0, %1, %2;" : "=l"(r) : "l"(a), "l"(b)); return r;
}
__device__ __forceinline__ u64 fma2(u64 a, u64 b, u64 c) {
    u64 r; asm("fma.rn.f32x2 %0, %1, %2, %3;" : "=l"(r) : "l"(a), "l"(b), "l"(c)); return r;
}
__device__ __forceinline__ u64 sub2(u64 a, u64 b, u64 neg1) { return fma2(b, neg1, a); }

__device__ __forceinline__ u64 shfl_dn64(u64 v) {
    unsigned lo = (unsigned)v, hi = (unsigned)(v >> 32);
    lo = __shfl_down_sync(0xffffffffu, lo, 1);
    hi = __shfl_down_sync(0xffffffffu, hi, 1);
    return ((u64)hi << 32) | lo;
}

// ---- macros over named local arrays (keep everything in registers) ----

#define LDROW(R, BP, BT) do {                                              \
    const float4* _pp = (const float4*)(Pp + (size_t)(R) * IMG_W);         \
    const float4* _tp = (const float4*)(Tp + (size_t)(R) * IMG_W);         \
    _Pragma("unroll") for (int _i = 0; _i < 4; ++_i) {                     \
        BP[_i] = __ldg(_pp + _i); BT[_i] = __ldg(_tp + _i);                \
    } } while (0)

#define ACCUM(BP, BT) do {                                                 \
    _Pragma("unroll") for (int _i = 0; _i < 4; ++_i) {                     \
        const float4 _a = BP[_i], _b = BT[_i];                             \
        u64 _w;                                                            \
        _w = pack2(_a.x, _b.x); CW[4*_i+0] = add2(CW[4*_i+0], _w);         \
        CQ[4*_i+0] = fma2(_w, _w, CQ[4*_i+0]);                             \
        CU[4*_i+0] = fmaf(_a.x, _b.x, CU[4*_i+0]);                         \
        _w = pack2(_a.y, _b.y); CW[4*_i+1] = add2(CW[4*_i+1], _w);         \
        CQ[4*_i+1] = fma2(_w, _w, CQ[4*_i+1]);                             \
        CU[4*_i+1] = fmaf(_a.y, _b.y, CU[4*_i+1]);                         \
        _w = pack2(_a.z, _b.z); CW[4*_i+2] = add2(CW[4*_i+2], _w);         \
        CQ[4*_i+2] = fma2(_w, _w, CQ[4*_i+2]);                             \
        CU[4*_i+2] = fmaf(_a.z, _b.z, CU[4*_i+2]);                         \
        _w = pack2(_a.w, _b.w); CW[4*_i+3] = add2(CW[4*_i+3], _w);         \
        CQ[4*_i+3] = fma2(_w, _w, CQ[4*_i+3]);                             \
        CU[4*_i+3] = fmaf(_a.w, _b.w, CU[4*_i+3]);                         \
    } } while (0)

#define SUBROW(BP, BT) do {                                                \
    _Pragma("unroll") for (int _i = 0; _i < 4; ++_i) {                     \
        const float4 _a = BP[_i], _b = BT[_i];                             \
        u64 _w, _q;                                                        \
        _w = pack2(_a.x, _b.x); CW[4*_i+0] = sub2(CW[4*_i+0], _w, NEG1);   \
        _q = mul2(_w, _w); CQ[4*_i+0] = sub2(CQ[4*_i+0], _q, NEG1);        \
        CU[4*_i+0] = fmaf(-_a.x, _b.x, CU[4*_i+0]);                        \
        _w = pack2(_a.y, _b.y); CW[4*_i+1] = sub2(CW[4*_i+1], _w, NEG1);   \
        _q = mul2(_w, _w); CQ[4*_i+1] = sub2(CQ[4*_i+1], _q, NEG1);        \
        CU[4*_i+1] = fmaf(-_a.y, _b.y, CU[4*_i+1]);                        \
        _w = pack2(_a.z, _b.z); CW[4*_i+2] = sub2(CW[4*_i+2], _w, NEG1);   \
        _q = mul2(_w, _w); CQ[4*_i+2] = sub2(CQ[4*_i+2], _q, NEG1);        \
        CU[4*_i+2] = fmaf(-_a.z, _b.z, CU[4*_i+2]);                        \
        _w = pack2(_a.w, _b.w); CW[4*_i+3] = sub2(CW[4*_i+3], _w, NEG1);   \
        _q = mul2(_w, _w); CQ[4*_i+3] = sub2(CQ[4*_i+3], _q, NEG1);        \
        CU[4*_i+3] = fmaf(-_a.w, _b.w, CU[4*_i+3]);                        \
    } } while (0)

#define GW(J) ((J) < 16 ? CW[(J)] : hW[(J) - 16])
#define GQ(J) ((J) < 16 ? CQ[(J)] : hQ[(J) - 16])
#define GU(J) ((J) < 16 ? CU[(J)] : hU[(J) - 16])

__global__ void __launch_bounds__(32, 8) ssim_kernel(const float* __restrict__ pred,
                                                     const float* __restrict__ targ,
                                                     float* __restrict__ out,
                                                     double inv_count, unsigned nblk)
{
    const int lane  = threadIdx.x;
    const int plane = blockIdx.x / NBANDS;
    const int band  = blockIdx.x % NBANDS;
    const size_t base = (size_t)plane * IMG_H * IMG_W
                      + (size_t)(band * BAND) * IMG_W + lane * 16;
    const float* __restrict__ Pp = pred + base;
    const float* __restrict__ Tp = targ + base;
    const int cb = lane * 16;                      // first output col of this lane

    const u64 NEG1  = pack2(-1.f, -1.f);
    const u64 C_TWO = pack2(2.f, 2.f);
    const u64 C_A   = pack2(0.96040004f, 0.96040004f);   // C1*49^2
    const u64 C_B   = pack2(8.6436f, 8.6436f);           // C2*49^2
    const u64 C_49  = pack2(49.f, 49.f);
    const u64 C_Q   = pack2(49.f/48.f, 49.f/48.f);
    const u64 C_2Q  = pack2(2.f*49.f/48.f, 2.f*49.f/48.f);

    // per-column vertical window sums: {Sx,Sy}, {Sxx,Syy}, Sxy
    u64 CW[16], CQ[16];
    float CU[16];
    #pragma unroll
    for (int i = 0; i < 16; ++i) { CW[i] = 0; CQ[i] = 0; CU[i] = 0.f; }

    float4 PA[4], TA[4], PB[4], TB[4];
    float acc = 0.f;

    // prime rows 0..5 (ping-pong; ends with bufA = row 6)
    LDROW(0, PA, TA);
    LDROW(1, PB, TB); ACCUM(PA, TA);
    LDROW(2, PA, TA); ACCUM(PB, TB);
    LDROW(3, PB, TB); ACCUM(PA, TA);
    LDROW(4, PA, TA); ACCUM(PB, TB);
    LDROW(5, PB, TB); ACCUM(PA, TA);
    LDROW(6, PA, TA); ACCUM(PB, TB);

#define EMIT() do {                                                         \
    u64 hW[6], hQ[6]; float hU[6];                                          \
    _Pragma("unroll") for (int _k = 0; _k < 6; ++_k) {                      \
        hW[_k] = shfl_dn64(CW[_k]); hQ[_k] = shfl_dn64(CQ[_k]);             \
        hU[_k] = __shfl_down_sync(0xffffffffu, CU[_k], 1);                  \
    }                                                                       \
    u64 VW = add2(add2(add2(CW[0], CW[1]), add2(CW[2], CW[3])),             \
                  add2(add2(CW[4], CW[5]), CW[6]));                         \
    u64 VQ = add2(add2(add2(CQ[0], CQ[1]), add2(CQ[2], CQ[3])),             \
                  add2(add2(CQ[4], CQ[5]), CQ[6]));                         \
    float VU = ((CU[0]+CU[1])+(CU[2]+CU[3]))+((CU[4]+CU[5])+CU[6]);         \
    _Pragma("unroll") for (int j = 0; j < 16; j += 2) {                     \
        u64 VW1 = add2(sub2(VW, GW(j), NEG1), GW(j+7));                     \
        u64 VQ1 = add2(sub2(VQ, GQ(j), NEG1), GQ(j+7));                     \
        float VU1 = VU - GU(j) + GU(j+7);                                   \
        float wx0,wy0,wx1,wy1,qx0,qy0,qx1,qy1;                              \
        unpack2(VW, wx0, wy0); unpack2(VW1, wx1, wy1);                      \
        unpack2(VQ, qx0, qy0); unpack2(VQ1, qx1, qy1);                      \
        const u64 X  = pack2(wx0, wx1), Y  = pack2(wy0, wy1);               \
        const u64 XX = pack2(qx0, qx1), YY = pack2(qy0, qy1);               \
        const u64 U  = pack2(VU, VU1);                                      \
        const u64 SXY = mul2(X, Y);                                         \
        const u64 N1  = fma2(C_TWO, SXY, C_A);                              \
        const u64 CC  = fma2(C_49, U, mul2(SXY, NEG1));                     \
        const u64 N2  = fma2(C_2Q, CC, C_B);                                \
        const u64 S2  = fma2(X, X, mul2(Y, Y));                             \
        const u64 D1  = add2(S2, C_A);                                      \
        const u64 TT  = fma2(C_49, add2(XX, YY), mul2(S2, NEG1));           \
        const u64 D2  = fma2(C_Q, TT, C_B);                                 \
        const u64 NUM = mul2(N1, N2), DEN = mul2(D1, D2);                   \
        float nA, nB, dA, dB;                                               \
        unpack2(NUM, nA, nB); unpack2(DEN, dA, dB);                         \
        if (cb + j     < OUT_W) acc += __fdividef(nA, dA);                  \
        if (cb + j + 1 < OUT_W) acc += __fdividef(nB, dB);                  \
        if (j < 14) {                                                       \
            VW = add2(sub2(VW1, GW(j+1), NEG1), GW(j+8));                   \
            VQ = add2(sub2(VQ1, GQ(j+1), NEG1), GQ(j+8));                   \
            VU = VU1 - GU(j+1) + GU(j+8);                                   \
        }                                                                   \
    } } while (0)

#define ITER(CP, CT, NP, NT_, R) do {                                       \
    if ((R) < BAND - 1) { LDROW((R) + 7, NP, NT_); }                        \
    float4 op[4], ot[4];                                                    \
    LDROW((R), op, ot);                                                     \
    ACCUM(CP, CT);                                                          \
    EMIT();                                                                 \
    SUBROW(op, ot);                                                         \
    } while (0)

    #pragma unroll 1
    for (int r = 0; r < BAND; r += 2) {
        ITER(PA, TA, PB, TB, r);
        ITER(PB, TB, PA, TA, r + 1);
    }

    // warp reduce -> atomic; last block finalizes and resets for graph replay
    #pragma unroll
    for (int off = 16; off > 0; off >>= 1)
        acc += __shfl_down_sync(0xffffffffu, acc, off);
    if (lane == 0) {
        atomicAdd(&g_acc, (double)acc);
        __threadfence();
        const unsigned old = atomicInc(&g_count, nblk - 1);
        if (old == nblk - 1) {
            __threadfence();
            const double v = atomicAdd(&g_acc, 0.0);
            out[0] = 1.0f - (float)(v * inv_count);
            __threadfence();
            g_acc = 0.0;
        }
    }
}

extern "C" void kernel_launch(void* const* d_in, const int* in_sizes, int n_in,
                              void* d_out, int out_size)
{
    const float* pred = (const float*)d_in[0];
    const float* targ = (const float*)d_in[1];
    const int planes = in_sizes[0] / (IMG_H * IMG_W);     // 96

    const unsigned blocks = (unsigned)planes * NBANDS;    // 1056
    const double inv_count = 1.0 / ((double)planes * OUT_H * OUT_W);

    ssim_kernel<<<blocks, 32>>>(pred, targ, (float*)d_out, inv_count, blocks);
}

// round 9
// speedup vs baseline: 2.2926x; 1.0489x over previous
#include <cuda_runtime.h>

#define IMG_H 512
#define IMG_W 512
#define OUT_H 506
#define OUT_W 506
#define BAND  46      // output rows per warp band (506 = 11*46)
#define NBANDS 11

typedef unsigned long long u64;

__device__ double g_acc;        // zero at module load; self-reset each launch
__device__ unsigned g_count;    // wraps to 0 via atomicInc each launch

__device__ __forceinline__ u64 pack2(float lo, float hi) {
    u64 r; asm("mov.b64 %0, {%1, %2};" : "=l"(r) : "f"(lo), "f"(hi)); return r;
}
__device__ __forceinline__ void unpack2(u64 v, float& lo, float& hi) {
    asm("mov.b64 {%0, %1}, %2;" : "=f"(lo), "=f"(hi) : "l"(v));
}
__device__ __forceinline__ u64 add2(u64 a, u64 b) {
    u64 r; asm("add.rn.f32x2 %0, %1, %2;" : "=l"(r) : "l"(a), "l"(b)); return r;
}
__device__ __forceinline__ u64 mul2(u64 a, u64 b) {
    u64 r; asm("mul.rn.f32x2 %0, %1, %2;" : "=l"(r) : "l"(a), "l"(b)); return r;
}
__device__ __forceinline__ u64 fma2(u64 a, u64 b, u64 c) {
    u64 r; asm("fma.rn.f32x2 %0, %1, %2, %3;" : "=l"(r) : "l"(a), "l"(b), "l"(c)); return r;
}
__device__ __forceinline__ u64 sub2(u64 a, u64 b, u64 neg1) { return fma2(b, neg1, a); }

__device__ __forceinline__ u64 shfl_dn64(u64 v) {
    unsigned lo = (unsigned)v, hi = (unsigned)(v >> 32);
    lo = __shfl_down_sync(0xffffffffu, lo, 1);
    hi = __shfl_down_sync(0xffffffffu, hi, 1);
    return ((u64)hi << 32) | lo;
}

#define LDROW(R, BP, BT) do {                                              \
    const float4* _pp = (const float4*)(Pp + (size_t)(R) * IMG_W);         \
    const float4* _tp = (const float4*)(Tp + (size_t)(R) * IMG_W);         \
    _Pragma("unroll") for (int _i = 0; _i < 4; ++_i) {                     \
        BP[_i] = __ldg(_pp + _i); BT[_i] = __ldg(_tp + _i);                \
    } } while (0)

// prologue: add-only accumulate of one row
#define ACCG(i, BP, BT) do {                                               \
    const float4 _a = BP[i], _b = BT[i];                                   \
    u64 _w;                                                                \
    _w = pack2(_a.x, _b.x); CW[4*(i)+0] = add2(CW[4*(i)+0], _w);           \
    CQ[4*(i)+0] = fma2(_w, _w, CQ[4*(i)+0]);                               \
    _w = pack2(_a.y, _b.y); CW[4*(i)+1] = add2(CW[4*(i)+1], _w);           \
    CQ[4*(i)+1] = fma2(_w, _w, CQ[4*(i)+1]);                               \
    _w = pack2(_a.z, _b.z); CW[4*(i)+2] = add2(CW[4*(i)+2], _w);           \
    CQ[4*(i)+2] = fma2(_w, _w, CQ[4*(i)+2]);                               \
    _w = pack2(_a.w, _b.w); CW[4*(i)+3] = add2(CW[4*(i)+3], _w);           \
    CQ[4*(i)+3] = fma2(_w, _w, CQ[4*(i)+3]);                               \
    CU2[2*(i)]   = fma2(pack2(_a.x,_a.y), pack2(_b.x,_b.y), CU2[2*(i)]);   \
    CU2[2*(i)+1] = fma2(pack2(_a.z,_a.w), pack2(_b.z,_b.w), CU2[2*(i)+1]); \
    } while (0)
#define ACC(BP, BT) do { ACCG(0,BP,BT); ACCG(1,BP,BT); ACCG(2,BP,BT); ACCG(3,BP,BT); } while (0)

// fused slide: add new row, subtract old row, via diff/sum factorization
#define FUSEDG(i, NPv, NTv, OPv, OTv) do {                                 \
    const float4 _an = NPv[i], _bn = NTv[i], _ao = OPv[i], _bo = OTv[i];   \
    u64 _wn, _wo, _d, _s;                                                  \
    _wn = pack2(_an.x,_bn.x); _wo = pack2(_ao.x,_bo.x);                    \
    _d = sub2(_wn,_wo,NEG1); _s = add2(_wn,_wo);                           \
    CW[4*(i)+0] = add2(CW[4*(i)+0], _d);                                   \
    CQ[4*(i)+0] = fma2(_d, _s, CQ[4*(i)+0]);                               \
    _wn = pack2(_an.y,_bn.y); _wo = pack2(_ao.y,_bo.y);                    \
    _d = sub2(_wn,_wo,NEG1); _s = add2(_wn,_wo);                           \
    CW[4*(i)+1] = add2(CW[4*(i)+1], _d);                                   \
    CQ[4*(i)+1] = fma2(_d, _s, CQ[4*(i)+1]);                               \
    _wn = pack2(_an.z,_bn.z); _wo = pack2(_ao.z,_bo.z);                    \
    _d = sub2(_wn,_wo,NEG1); _s = add2(_wn,_wo);                           \
    CW[4*(i)+2] = add2(CW[4*(i)+2], _d);                                   \
    CQ[4*(i)+2] = fma2(_d, _s, CQ[4*(i)+2]);                               \
    _wn = pack2(_an.w,_bn.w); _wo = pack2(_ao.w,_bo.w);                    \
    _d = sub2(_wn,_wo,NEG1); _s = add2(_wn,_wo);                           \
    CW[4*(i)+3] = add2(CW[4*(i)+3], _d);                                   \
    CQ[4*(i)+3] = fma2(_d, _s, CQ[4*(i)+3]);                               \
    {   u64 _un = mul2(pack2(_an.x,_an.y), pack2(_bn.x,_bn.y));            \
        u64 _uo = mul2(pack2(_ao.x,_ao.y), pack2(_bo.x,_bo.y));            \
        CU2[2*(i)]   = add2(CU2[2*(i)], _un);                              \
        CU2[2*(i)]   = sub2(CU2[2*(i)], _uo, NEG1); }                      \
    {   u64 _un = mul2(pack2(_an.z,_an.w), pack2(_bn.z,_bn.w));            \
        u64 _uo = mul2(pack2(_ao.z,_ao.w), pack2(_bo.z,_bo.w));            \
        CU2[2*(i)+1] = add2(CU2[2*(i)+1], _un);                            \
        CU2[2*(i)+1] = sub2(CU2[2*(i)+1], _uo, NEG1); }                    \
    } while (0)
#define FUSED(NPv,NTv,OPv,OTv) do { FUSEDG(0,NPv,NTv,OPv,OTv); FUSEDG(1,NPv,NTv,OPv,OTv); \
                                    FUSEDG(2,NPv,NTv,OPv,OTv); FUSEDG(3,NPv,NTv,OPv,OTv); } while (0)

#define GW(J) ((J) < 16 ? CW[(J)] : hW[(J) - 16])
#define GQ(J) ((J) < 16 ? CQ[(J)] : hQ[(J) - 16])

#define EMIT() do {                                                         \
    u64 hW[6], hQ[6], hU2[3];                                               \
    _Pragma("unroll") for (int _k = 0; _k < 6; ++_k) {                      \
        hW[_k] = shfl_dn64(CW[_k]); hQ[_k] = shfl_dn64(CQ[_k]);             \
    }                                                                       \
    _Pragma("unroll") for (int _k = 0; _k < 3; ++_k)                        \
        hU2[_k] = shfl_dn64(CU2[_k]);                                       \
    float Ua[22];                                                           \
    _Pragma("unroll") for (int _k = 0; _k < 8; ++_k)                        \
        unpack2(CU2[_k], Ua[2*_k], Ua[2*_k+1]);                             \
    _Pragma("unroll") for (int _k = 0; _k < 3; ++_k)                        \
        unpack2(hU2[_k], Ua[16+2*_k], Ua[17+2*_k]);                         \
    u64 VW = add2(add2(add2(CW[0],CW[1]),add2(CW[2],CW[3])),                \
                  add2(add2(CW[4],CW[5]),CW[6]));                           \
    u64 VQ = add2(add2(add2(CQ[0],CQ[1]),add2(CQ[2],CQ[3])),                \
                  add2(add2(CQ[4],CQ[5]),CQ[6]));                           \
    float VU = ((Ua[0]+Ua[1])+(Ua[2]+Ua[3]))+((Ua[4]+Ua[5])+Ua[6]);         \
    float gr = 0.f, gq = 1.f;                                               \
    _Pragma("unroll") for (int j = 0; j < 16; j += 2) {                     \
        u64 VW1 = add2(sub2(VW, GW(j), NEG1), GW(j+7));                     \
        u64 VQ1 = add2(sub2(VQ, GQ(j), NEG1), GQ(j+7));                     \
        float VU1 = VU - Ua[j] + Ua[j+7];                                   \
        float wx0,wy0,wx1,wy1,qx0,qy0,qx1,qy1;                              \
        unpack2(VW, wx0, wy0); unpack2(VW1, wx1, wy1);                      \
        unpack2(VQ, qx0, qy0); unpack2(VQ1, qx1, qy1);                      \
        const u64 X  = pack2(wx0, wx1), Y  = pack2(wy0, wy1);               \
        const u64 XX = pack2(qx0, qx1), YY = pack2(qy0, qy1);               \
        const u64 Uu = pack2(VU, VU1);                                      \
        const u64 SXY = mul2(X, Y);                                         \
        const u64 N1v = fma2(C_TWO, SXY, C_A);                              \
        const u64 CCv = fma2(C_49, Uu, mul2(SXY, NEG1));                    \
        const u64 N2v = fma2(C_2Q, CCv, C_B);                               \
        const u64 S2v = fma2(X, X, mul2(Y, Y));                             \
        const u64 D1v = add2(S2v, C_A);                                     \
        const u64 TTv = fma2(C_49, add2(XX, YY), mul2(S2v, NEG1));          \
        const u64 D2v = fma2(C_Q, TTv, C_B);                                \
        const u64 NUMv = mul2(N1v, N2v), DENv = mul2(D1v, D2v);             \
        float n0, n1, d0, d1;                                               \
        unpack2(NUMv, n0, n1); unpack2(DENv, d0, d1);                       \
        if (j >= 10) {   /* only cols >= 506 can be invalid (lane 31) */    \
            if (cb + j     >= OUT_W) { n0 = 0.f; d0 = 1.f; }                \
            if (cb + j + 1 >= OUT_W) { n1 = 0.f; d1 = 1.f; }                \
        }                                                                   \
        const float r2 = fmaf(n0, d1, n1 * d0);                             \
        const float q2 = d0 * d1;                                           \
        if ((j & 2) == 0) { gr = r2; gq = q2; }                             \
        else { acc += __fdividef(fmaf(gr, q2, r2 * gq), gq * q2); }         \
        if (j < 14) {                                                       \
            VW = add2(sub2(VW1, GW(j+1), NEG1), GW(j+8));                   \
            VQ = add2(sub2(VQ1, GQ(j+1), NEG1), GQ(j+8));                   \
            VU = VU1 - Ua[j+1] + Ua[j+8];                                   \
        }                                                                   \
    } } while (0)

__global__ void __launch_bounds__(32, 8) ssim_kernel(const float* __restrict__ pred,
                                                     const float* __restrict__ targ,
                                                     float* __restrict__ out,
                                                     double inv_count, unsigned nblk)
{
    const int lane  = threadIdx.x;
    const int plane = blockIdx.x / NBANDS;
    const int band  = blockIdx.x % NBANDS;
    const size_t base = (size_t)plane * IMG_H * IMG_W
                      + (size_t)(band * BAND) * IMG_W + lane * 16;
    const float* __restrict__ Pp = pred + base;
    const float* __restrict__ Tp = targ + base;
    const int cb = lane * 16;

    const u64 NEG1  = pack2(-1.f, -1.f);
    const u64 C_TWO = pack2(2.f, 2.f);
    const u64 C_A   = pack2(0.96040004f, 0.96040004f);   // C1*49^2
    const u64 C_B   = pack2(8.6436f, 8.6436f);           // C2*49^2
    const u64 C_49  = pack2(49.f, 49.f);
    const u64 C_Q   = pack2(49.f/48.f, 49.f/48.f);
    const u64 C_2Q  = pack2(2.f*49.f/48.f, 2.f*49.f/48.f);

    u64 CW[16], CQ[16], CU2[8];
    #pragma unroll
    for (int i = 0; i < 16; ++i) { CW[i] = 0; CQ[i] = 0; }
    #pragma unroll
    for (int i = 0; i < 8; ++i) CU2[i] = 0;

    float4 PN0[4], TN0[4], PN1[4], TN1[4];
    float4 PO0[4], TO0[4], PO1[4], TO1[4];
    float acc = 0.f;

    // prologue: accumulate rows 0..5 (ping-pong to overlap loads)
    LDROW(0, PN0, TN0);
    LDROW(1, PN1, TN1); ACC(PN0, TN0);
    LDROW(2, PN0, TN0); ACC(PN1, TN1);
    LDROW(3, PN1, TN1); ACC(PN0, TN0);
    LDROW(4, PN0, TN0); ACC(PN1, TN1);
    LDROW(5, PN1, TN1); ACC(PN0, TN0);
    ACC(PN1, TN1);
    LDROW(6, PN0, TN0);                       // new row for iter 0
    #pragma unroll
    for (int i = 0; i < 4; ++i) {             // old "row -1" = zeros for iter 0
        PO0[i] = make_float4(0.f,0.f,0.f,0.f);
        TO0[i] = make_float4(0.f,0.f,0.f,0.f);
    }

    #pragma unroll 1
    for (int r = 0; r < BAND; r += 2) {
        // ---- even iter r: window rows r..r+6, consumes PN0 (row r+6), PO0 (row r-1)
        LDROW(r + 7, PN1, TN1);               // new for iter r+1 (r<=44 -> row<=51, in-bounds)
        LDROW(r,     PO1, TO1);               // old for iter r+1
        FUSED(PN0, TN0, PO0, TO0);
        EMIT();
        // ---- odd iter r+1: consumes PN1 (row r+7), PO1 (row r)
        if (r + 2 < BAND) LDROW(r + 8, PN0, TN0);   // new for iter r+2
        LDROW(r + 1, PO0, TO0);               // old for iter r+2 (in-bounds even at r=44)
        FUSED(PN1, TN1, PO1, TO1);
        EMIT();
    }

    // warp reduce -> atomic; last block finalizes and resets for graph replay
    #pragma unroll
    for (int off = 16; off > 0; off >>= 1)
        acc += __shfl_down_sync(0xffffffffu, acc, off);
    if (lane == 0) {
        atomicAdd(&g_acc, (double)acc);
        __threadfence();
        const unsigned old = atomicInc(&g_count, nblk - 1);
        if (old == nblk - 1) {
            __threadfence();
            const double v = atomicAdd(&g_acc, 0.0);
            out[0] = 1.0f - (float)(v * inv_count);
            __threadfence();
            g_acc = 0.0;
        }
    }
}

extern "C" void kernel_launch(void* const* d_in, const int* in_sizes, int n_in,
                              void* d_out, int out_size)
{
    const float* pred = (const float*)d_in[0];
    const float* targ = (const float*)d_in[1];
    const int planes = in_sizes[0] / (IMG_H * IMG_W);     // 96

    const unsigned blocks = (unsigned)planes * NBANDS;    // 1056
    const double inv_count = 1.0 / ((double)planes * OUT_H * OUT_W);

    ssim_kernel<<<blocks, 32>>>(pred, targ, (float*)d_out, inv_count, blocks);
}